// round 4
// baseline (speedup 1.0000x reference)
#include <cuda_runtime.h>
#include <cuda_bf16.h>

// Problem constants (SppPooling: GRID=16, K_MAX=32, D=256)
#define GRIDSZ 16
#define RCELLS (GRIDSZ * GRIDSZ)   // 256
#define KMAX   32
#define FEAT_D 256
#define FIELDS (3 + KMAX)          // 35 int32 per xy row (JAX downcasts int64->int32)
#define CELLS_PER_BLK 32
#define MAX_B 64

// Scratch: inverse permutation cell -> r, per batch.
__device__ int g_inv[MAX_B * RCELLS];

// ---------------------------------------------------------------------------
// Kernel 0: init inverse map to -1
// ---------------------------------------------------------------------------
__global__ void init_inv_kernel(int total) {
    int i = blockIdx.x * blockDim.x + threadIdx.x;
    if (i < total) g_inv[i] = -1;
}

// ---------------------------------------------------------------------------
// Kernel 1: scatter r into g_inv[b][row*16+col]
// ---------------------------------------------------------------------------
__global__ void build_inv_kernel(const int* __restrict__ xy,
                                 int n_per, int B) {
    int i = blockIdx.x * blockDim.x + threadIdx.x;   // b*RCELLS + r
    if (i >= B * RCELLS) return;
    int b = i / RCELLS;
    int r = i % RCELLS;
    const int* row = xy + (size_t)(b * n_per + r) * FIELDS;
    int rr = row[0];
    if (rr >= 0) {
        int cc = row[1];
        int cell = rr * GRIDSZ + cc;
        if (cell >= 0 && cell < RCELLS)
            g_inv[b * RCELLS + cell] = r;
    }
}

// ---------------------------------------------------------------------------
// Kernel 2: pooled gather + transposed coalesced store.
// Block = (batch b, cell-group g of 32 consecutive output cells).
// 256 threads: thread tid owns feature column d = tid during accumulation,
// then the block transposes through smem so each warp writes 32 consecutive
// output floats (128B contiguous stores).
// ---------------------------------------------------------------------------
__global__ __launch_bounds__(FEAT_D, 4)
void spp_pool_kernel(const float* __restrict__ F,
                     const int* __restrict__ xy,
                     float* __restrict__ out,
                     int n_per) {
    const int b   = blockIdx.x;
    const int g   = blockIdx.y;          // 0..7
    const int tid = threadIdx.x;         // 0..255

    __shared__ int   s_r[CELLS_PER_BLK];
    __shared__ int   s_cnt[CELLS_PER_BLK];
    __shared__ int   s_ind[CELLS_PER_BLK][KMAX];
    __shared__ float s_t[FEAT_D][CELLS_PER_BLK + 1];  // +1 pad: conflict-free

    // 1) Fetch source row index r for each of this block's 32 cells.
    if (tid < CELLS_PER_BLK) {
        int cell = g * CELLS_PER_BLK + tid;
        s_r[tid] = g_inv[b * RCELLS + cell];
    }
    __syncthreads();

    // 2) Load metadata (count + 32 indices) for 32 cells: 1056 entries.
    for (int e = tid; e < CELLS_PER_BLK * (KMAX + 1); e += FEAT_D) {
        int c = e / (KMAX + 1);
        int f = e % (KMAX + 1);
        int r = s_r[c];
        int v = 0;
        if (r >= 0) {
            const int* row = xy + (size_t)(b * n_per + r) * FIELDS;
            v = row[2 + f];          // f==0 -> count, f>=1 -> ind[f-1]
        }
        if (f == 0) s_cnt[c] = v;
        else        s_ind[c][f - 1] = v;
    }
    __syncthreads();

    // 3) Accumulate: thread tid handles column d=tid for all 32 cells.
    const float* __restrict__ Fb = F + (size_t)b * n_per * FEAT_D + tid;
    for (int c = 0; c < CELLS_PER_BLK; c++) {
        int cnt = s_cnt[c];
        float a0 = 0.f, a1 = 0.f, a2 = 0.f, a3 = 0.f;
        int k = 0;
        #pragma unroll 1
        for (; k + 4 <= cnt; k += 4) {
            int i0 = s_ind[c][k + 0];
            int i1 = s_ind[c][k + 1];
            int i2 = s_ind[c][k + 2];
            int i3 = s_ind[c][k + 3];
            a0 += Fb[(size_t)i0 * FEAT_D];
            a1 += Fb[(size_t)i1 * FEAT_D];
            a2 += Fb[(size_t)i2 * FEAT_D];
            a3 += Fb[(size_t)i3 * FEAT_D];
        }
        for (; k < cnt; k++) {
            a0 += Fb[(size_t)s_ind[c][k] * FEAT_D];
        }
        int   dn   = cnt > 1 ? cnt : 1;
        float scal = 1.0f / (float)dn;
        s_t[tid][c] = ((a0 + a1) + (a2 + a3)) * scal;   // stride 33: no conflicts
    }
    __syncthreads();

    // 4) Transposed coalesced store: warp = one d, 32 consecutive cells.
    float* __restrict__ ob = out + (size_t)b * FEAT_D * RCELLS + g * CELLS_PER_BLK;
    #pragma unroll
    for (int it = 0; it < CELLS_PER_BLK; it++) {        // 32 iters x 256 thr
        int e  = it * FEAT_D + tid;
        int d  = e >> 5;          // 0..255
        int cl = e & 31;          // lane = cell offset -> contiguous 128B/warp
        ob[(size_t)d * RCELLS + cl] = s_t[d][cl];
    }
}

// ---------------------------------------------------------------------------
extern "C" void kernel_launch(void* const* d_in, const int* in_sizes, int n_in,
                              void* d_out, int out_size) {
    const float* F  = (const float*)d_in[0];
    const int*   xy = (const int*)d_in[1];   // int32 (JAX default, no x64)

    int B     = in_sizes[2];                          // 64
    int n_per = in_sizes[0] / (B * FEAT_D);           // 2048
    float* out = (float*)d_out;

    int total_inv = B * RCELLS;
    init_inv_kernel<<<(total_inv + 255) / 256, 256>>>(total_inv);
    build_inv_kernel<<<(total_inv + 255) / 256, 256>>>(xy, n_per, B);

    dim3 grid(B, RCELLS / CELLS_PER_BLK);             // (64, 8)
    spp_pool_kernel<<<grid, FEAT_D>>>(F, xy, out, n_per);
}

// round 5
// speedup vs baseline: 2.6378x; 2.6378x over previous
#include <cuda_runtime.h>
#include <cuda_bf16.h>

// SppPooling: GRID=16, K_MAX=32, D=256, R=256 cells/batch, xy rows = 35 int32
#define GRIDSZ 16
#define RCELLS (GRIDSZ * GRIDSZ)   // 256
#define KMAX   32
#define FEAT_D 256
#define FIELDS (3 + KMAX)          // 35 int32 per xy row
#define CELLS_PER_BLK 32
#define CELLS_PER_WARP 4           // 8 warps * 4 = 32
#define TSTRIDE4 65                // float4 stride for transpose buffer (pad)

// ---------------------------------------------------------------------------
// Single fused kernel.
// Block = (cell-group g = blockIdx.x in 0..7, batch b = blockIdx.y).
// Grid order (8, B): wave-1 spans ~19 batches -> 38MB working set fits L2,
// preserving the ~2.1x gather reuse in L2 instead of spilling to DRAM.
//
// Phase 0: block scans the 256 header rows of its batch, builds cell->r for
//          its 32 cells in smem (replaces the old 2 pre-kernels).
// Phase 1: metadata (count + 32 inds) for 32 cells -> smem.
// Phase 2: warp w owns 4 cells; lanes accumulate float4 columns
//          (2x LDG.128 per row, 2 rows in flight = 64B/thread MLP).
// Phase 3: smem transpose -> warp writes 32 consecutive cells per d
//          (128B fully-coalesced stores).
// ---------------------------------------------------------------------------
__global__ __launch_bounds__(FEAT_D, 4)
void spp_pool_kernel(const float* __restrict__ F,
                     const int* __restrict__ xy,
                     float* __restrict__ out,
                     int n_per) {
    const int g    = blockIdx.x;         // 0..7 cell group
    const int b    = blockIdx.y;         // batch
    const int tid  = threadIdx.x;        // 0..255
    const int w    = tid >> 5;           // warp 0..7
    const int lane = tid & 31;

    __shared__ int    s_r[CELLS_PER_BLK];
    __shared__ int    s_cnt[CELLS_PER_BLK];
    __shared__ int    s_ind[CELLS_PER_BLK][KMAX];
    __shared__ float4 s_t4[CELLS_PER_BLK][TSTRIDE4];  // [cell][d4], 33.3KB

    const int* xyb = xy + (size_t)b * n_per * FIELDS;

    // ---- Phase 0: find source row r for each of this block's 32 cells ----
    if (tid < CELLS_PER_BLK) s_r[tid] = -1;
    __syncthreads();
    {
        // r = tid scans all 256 header rows of this batch
        const int* row = xyb + (size_t)tid * FIELDS;
        int rr = row[0];
        if (rr >= 0) {
            int cell = rr * GRIDSZ + row[1];
            int c = cell - g * CELLS_PER_BLK;
            if (c >= 0 && c < CELLS_PER_BLK) s_r[c] = tid;
        }
    }
    __syncthreads();

    // ---- Phase 1: metadata (count + 32 indices) for 32 cells ----
    for (int e = tid; e < CELLS_PER_BLK * (KMAX + 1); e += FEAT_D) {
        int c = e / (KMAX + 1);
        int f = e % (KMAX + 1);
        int r = s_r[c];
        int v = 0;
        if (r >= 0) v = xyb[(size_t)r * FIELDS + 2 + f];
        if (f == 0) s_cnt[c] = v;
        else        s_ind[c][f - 1] = v;
    }
    __syncthreads();

    // ---- Phase 2: accumulate. Warp w owns cells w*4 .. w*4+3 ----
    const float4* __restrict__ Fb =
        (const float4*)(F + (size_t)b * n_per * FEAT_D);

    #pragma unroll
    for (int cc = 0; cc < CELLS_PER_WARP; cc++) {
        int c   = w * CELLS_PER_WARP + cc;
        int cnt = s_cnt[c];

        float4 alo0 = make_float4(0.f, 0.f, 0.f, 0.f);
        float4 ahi0 = make_float4(0.f, 0.f, 0.f, 0.f);
        float4 alo1 = make_float4(0.f, 0.f, 0.f, 0.f);
        float4 ahi1 = make_float4(0.f, 0.f, 0.f, 0.f);

        int k = 0;
        #pragma unroll 1
        for (; k + 2 <= cnt; k += 2) {
            int i0 = s_ind[c][k + 0];
            int i1 = s_ind[c][k + 1];
            const float4* r0 = Fb + (size_t)i0 * (FEAT_D / 4);
            const float4* r1 = Fb + (size_t)i1 * (FEAT_D / 4);
            float4 v0l = r0[lane];
            float4 v0h = r0[lane + 32];
            float4 v1l = r1[lane];
            float4 v1h = r1[lane + 32];
            alo0.x += v0l.x; alo0.y += v0l.y; alo0.z += v0l.z; alo0.w += v0l.w;
            ahi0.x += v0h.x; ahi0.y += v0h.y; ahi0.z += v0h.z; ahi0.w += v0h.w;
            alo1.x += v1l.x; alo1.y += v1l.y; alo1.z += v1l.z; alo1.w += v1l.w;
            ahi1.x += v1h.x; ahi1.y += v1h.y; ahi1.z += v1h.z; ahi1.w += v1h.w;
        }
        if (k < cnt) {
            int i0 = s_ind[c][k];
            const float4* r0 = Fb + (size_t)i0 * (FEAT_D / 4);
            float4 v0l = r0[lane];
            float4 v0h = r0[lane + 32];
            alo0.x += v0l.x; alo0.y += v0l.y; alo0.z += v0l.z; alo0.w += v0l.w;
            ahi0.x += v0h.x; ahi0.y += v0h.y; ahi0.z += v0h.z; ahi0.w += v0h.w;
        }

        float scal = 1.0f / (float)(cnt > 1 ? cnt : 1);
        float4 rl, rh;
        rl.x = (alo0.x + alo1.x) * scal; rl.y = (alo0.y + alo1.y) * scal;
        rl.z = (alo0.z + alo1.z) * scal; rl.w = (alo0.w + alo1.w) * scal;
        rh.x = (ahi0.x + ahi1.x) * scal; rh.y = (ahi0.y + ahi1.y) * scal;
        rh.z = (ahi0.z + ahi1.z) * scal; rh.w = (ahi0.w + ahi1.w) * scal;

        s_t4[c][lane]      = rl;   // consecutive lanes -> conflict-free
        s_t4[c][lane + 32] = rh;
    }
    __syncthreads();

    // ---- Phase 3: transposed coalesced store ----
    // out[b][d][cell]; warp writes 32 consecutive cells for one d (128B).
    const float* s_tf = (const float*)s_t4;   // element (c,d) at c*4*TSTRIDE4 + d
    float* __restrict__ ob =
        out + (size_t)b * FEAT_D * RCELLS + g * CELLS_PER_BLK;
    #pragma unroll
    for (int it = 0; it < CELLS_PER_BLK; it++) {   // 32 iters x 256 threads
        int e  = it * FEAT_D + tid;
        int d  = e >> 5;           // 0..255
        int cl = e & 31;           // lane = cell offset
        ob[(size_t)d * RCELLS + cl] = s_tf[cl * (4 * TSTRIDE4) + d];
    }
}

// ---------------------------------------------------------------------------
extern "C" void kernel_launch(void* const* d_in, const int* in_sizes, int n_in,
                              void* d_out, int out_size) {
    const float* F  = (const float*)d_in[0];
    const int*   xy = (const int*)d_in[1];   // int32 (JAX default, no x64)

    int B     = in_sizes[2];                          // 64
    int n_per = in_sizes[0] / (B * FEAT_D);           // 2048
    float* out = (float*)d_out;

    dim3 grid(RCELLS / CELLS_PER_BLK, B);             // (8, 64): batch-major waves
    spp_pool_kernel<<<grid, FEAT_D>>>(F, xy, out, n_per);
}

// round 7
// speedup vs baseline: 3.0647x; 1.1619x over previous
#include <cuda_runtime.h>
#include <cuda_bf16.h>

// SppPooling: GRID=16, K_MAX=32, D=256, R=256 cells/batch, xy rows = 35 int32
#define GRIDSZ 16
#define RCELLS (GRIDSZ * GRIDSZ)   // 256
#define KMAX   32
#define FEAT_D 256
#define FIELDS (3 + KMAX)          // 35 int32 per xy row
#define CELLS_PER_BLK 32
#define CELLS_PER_WARP 4           // 8 warps * 4 = 32
#define TSTRIDE4 65                // float4 stride for transpose buffer (pad)

__device__ __forceinline__ void add4(float4& a, const float4& v) {
    a.x += v.x; a.y += v.y; a.z += v.z; a.w += v.w;
}

// ---------------------------------------------------------------------------
// Single fused kernel.
// Block = (cell-group g = blockIdx.x in 0..7, batch b = blockIdx.y).
// Grid order (8, B): wave-1 spans ~19 batches -> working set fits L2, so the
// ~2.1x gather reuse stays in L2 (DRAM traffic stays at the 134MB unique floor).
//
// Phase 0: block scans the 256 header rows of its batch, builds cell->r.
// Phase 1: metadata (count + 32 inds) for 32 cells -> smem.
// Phase 2: warp w owns 4 cells; 4-row unrolled gather: 8x LDG.128 in flight
//          per thread (128B/thread MLP) -> halves the exposed-latency chain.
// Phase 3: smem transpose -> warp writes 32 consecutive cells per d
//          (128B fully-coalesced stores).
// ---------------------------------------------------------------------------
__global__ __launch_bounds__(FEAT_D, 4)
void spp_pool_kernel(const float* __restrict__ F,
                     const int* __restrict__ xy,
                     float* __restrict__ out,
                     int n_per) {
    const int g    = blockIdx.x;         // 0..7 cell group
    const int b    = blockIdx.y;         // batch
    const int tid  = threadIdx.x;        // 0..255
    const int w    = tid >> 5;           // warp 0..7
    const int lane = tid & 31;

    __shared__ int    s_r[CELLS_PER_BLK];
    __shared__ int    s_cnt[CELLS_PER_BLK];
    __shared__ int    s_ind[CELLS_PER_BLK][KMAX];
    __shared__ float4 s_t4[CELLS_PER_BLK][TSTRIDE4];  // [cell][d4], 33.3KB

    const int* xyb = xy + (size_t)b * n_per * FIELDS;

    // ---- Phase 0: find source row r for each of this block's 32 cells ----
    if (tid < CELLS_PER_BLK) s_r[tid] = -1;
    __syncthreads();
    {
        const int* row = xyb + (size_t)tid * FIELDS;   // r = tid scans headers
        int rr = row[0];
        if (rr >= 0) {
            int cell = rr * GRIDSZ + row[1];
            int c = cell - g * CELLS_PER_BLK;
            if (c >= 0 && c < CELLS_PER_BLK) s_r[c] = tid;
        }
    }
    __syncthreads();

    // ---- Phase 1: metadata (count + 32 indices) for 32 cells ----
    for (int e = tid; e < CELLS_PER_BLK * (KMAX + 1); e += FEAT_D) {
        int c = e / (KMAX + 1);
        int f = e % (KMAX + 1);
        int r = s_r[c];
        int v = 0;
        if (r >= 0) v = xyb[(size_t)r * FIELDS + 2 + f];
        if (f == 0) s_cnt[c] = v;
        else        s_ind[c][f - 1] = v;
    }
    __syncthreads();

    // ---- Phase 2: accumulate. Warp w owns cells w*4 .. w*4+3 ----
    const float4* __restrict__ Fb =
        (const float4*)(F + (size_t)b * n_per * FEAT_D);

    #pragma unroll
    for (int cc = 0; cc < CELLS_PER_WARP; cc++) {
        int c   = w * CELLS_PER_WARP + cc;
        int cnt = s_cnt[c];

        float4 alo = make_float4(0.f, 0.f, 0.f, 0.f);
        float4 ahi = make_float4(0.f, 0.f, 0.f, 0.f);

        int k = 0;
        #pragma unroll 1
        for (; k + 4 <= cnt; k += 4) {
            const float4* r0 = Fb + (size_t)s_ind[c][k + 0] * (FEAT_D / 4);
            const float4* r1 = Fb + (size_t)s_ind[c][k + 1] * (FEAT_D / 4);
            const float4* r2 = Fb + (size_t)s_ind[c][k + 2] * (FEAT_D / 4);
            const float4* r3 = Fb + (size_t)s_ind[c][k + 3] * (FEAT_D / 4);
            // 8 LDG.128 issued before any consumption: 128B/thread in flight
            float4 v0l = r0[lane];      float4 v1l = r1[lane];
            float4 v2l = r2[lane];      float4 v3l = r3[lane];
            float4 v0h = r0[lane + 32]; float4 v1h = r1[lane + 32];
            float4 v2h = r2[lane + 32]; float4 v3h = r3[lane + 32];
            // pairwise: short FADD chains
            add4(v0l, v1l); add4(v2l, v3l); add4(alo, v0l); add4(alo, v2l);
            add4(v0h, v1h); add4(v2h, v3h); add4(ahi, v0h); add4(ahi, v2h);
        }
        #pragma unroll 1
        for (; k < cnt; k++) {
            const float4* r0 = Fb + (size_t)s_ind[c][k] * (FEAT_D / 4);
            float4 v0l = r0[lane];
            float4 v0h = r0[lane + 32];
            add4(alo, v0l);
            add4(ahi, v0h);
        }

        float scal = 1.0f / (float)(cnt > 1 ? cnt : 1);
        float4 rl, rh;
        rl.x = alo.x * scal; rl.y = alo.y * scal;
        rl.z = alo.z * scal; rl.w = alo.w * scal;
        rh.x = ahi.x * scal; rh.y = ahi.y * scal;
        rh.z = ahi.z * scal; rh.w = ahi.w * scal;

        s_t4[c][lane]      = rl;   // consecutive lanes -> conflict-free
        s_t4[c][lane + 32] = rh;
    }
    __syncthreads();

    // ---- Phase 3: transposed coalesced store ----
    // out[b][d][cell]; warp writes 32 consecutive cells for one d (128B).
    const float* s_tf = (const float*)s_t4;   // element (c,d) at c*4*TSTRIDE4 + d
    float* __restrict__ ob =
        out + (size_t)b * FEAT_D * RCELLS + g * CELLS_PER_BLK;
    #pragma unroll
    for (int it = 0; it < CELLS_PER_BLK; it++) {   // 32 iters x 256 threads
        int e  = it * FEAT_D + tid;
        int d  = e >> 5;           // 0..255
        int cl = e & 31;           // lane = cell offset
        ob[(size_t)d * RCELLS + cl] = s_tf[cl * (4 * TSTRIDE4) + d];
    }
}

// ---------------------------------------------------------------------------
extern "C" void kernel_launch(void* const* d_in, const int* in_sizes, int n_in,
                              void* d_out, int out_size) {
    const float* F  = (const float*)d_in[0];
    const int*   xy = (const int*)d_in[1];   // int32 (JAX default, no x64)

    int B     = in_sizes[2];                          // 64
    int n_per = in_sizes[0] / (B * FEAT_D);           // 2048
    float* out = (float*)d_out;

    dim3 grid(RCELLS / CELLS_PER_BLK, B);             // (8, 64): batch-major waves
    spp_pool_kernel<<<grid, FEAT_D>>>(F, xy, out, n_per);
}